// round 2
// baseline (speedup 1.0000x reference)
#include <cuda_runtime.h>
#include <math.h>
#include <stdint.h>

#define BATCH   32
#define SQ      512
#define DM      512
#define DFF     2048
#define NH      8
#define HD      64
#define TOKENS  (BATCH * SQ)   // 16384

// ---------------- scratch (device globals; no runtime allocation) ----------
__device__ float g_Q  [TOKENS * DM];
__device__ float g_K  [TOKENS * DM];
__device__ float g_V  [TOKENS * DM];
__device__ float g_Ctx[TOKENS * DM];
__device__ float g_T1 [TOKENS * DM];
__device__ float g_A  [TOKENS * DM];
__device__ float g_H  [TOKENS * DFF];
__device__ float g_T2 [TOKENS * DM];

// ---------------- tiled SGEMM: C = A[MxK] @ B[KxN] + bias (+epilogue) ------
// EPI: 0 = bias only, 1 = bias + exact GELU, 2 = bias + residual
#define BM 128
#define BN 128
#define BK 8

__device__ __forceinline__ float gelu_exact(float v) {
    return 0.5f * v * (1.0f + erff(v * 0.70710678118654752f));
}

template <int EPI>
__global__ __launch_bounds__(256) void sgemm_kernel(
    const float* __restrict__ A, const float* __restrict__ B,
    const float* __restrict__ bias, const float* __restrict__ res,
    float* __restrict__ C, int M, int N, int K)
{
    __shared__ float As[BK][132];   // padded: conflict-free transposed stores
    __shared__ float Bs[BK][BN];

    const int tid  = threadIdx.x;
    const int row0 = blockIdx.y * BM;
    const int col0 = blockIdx.x * BN;

    // A loader: thread -> A[row0 + tid/2][(tid&1)*4 .. +3]
    const int a_r = tid >> 1;
    const int a_c = (tid & 1) << 2;
    // B loader: thread -> B[tid/32][col0 + (tid&31)*4 .. +3]
    const int b_r = tid >> 5;
    const int b_c = (tid & 31) << 2;

    const int tx = tid & 15;   // owns cols {tx + 16*j}
    const int ty = tid >> 4;   // owns rows {ty + 16*i}

    float acc[8][8];
    #pragma unroll
    for (int i = 0; i < 8; i++)
        #pragma unroll
        for (int j = 0; j < 8; j++) acc[i][j] = 0.f;

    const float* Aptr = A + (size_t)(row0 + a_r) * K + a_c;
    const float* Bptr = B + (size_t)b_r * N + col0 + b_c;

    for (int k0 = 0; k0 < K; k0 += BK) {
        float4 av = *(const float4*)(Aptr + k0);
        As[a_c + 0][a_r] = av.x;
        As[a_c + 1][a_r] = av.y;
        As[a_c + 2][a_r] = av.z;
        As[a_c + 3][a_r] = av.w;
        float4 bv = *(const float4*)(Bptr + (size_t)k0 * N);
        *(float4*)&Bs[b_r][b_c] = bv;
        __syncthreads();

        #pragma unroll
        for (int k = 0; k < BK; k++) {
            float ra[8], rb[8];
            #pragma unroll
            for (int i = 0; i < 8; i++) ra[i] = As[k][i * 16 + ty];
            #pragma unroll
            for (int j = 0; j < 8; j++) rb[j] = Bs[k][j * 16 + tx];
            #pragma unroll
            for (int i = 0; i < 8; i++)
                #pragma unroll
                for (int j = 0; j < 8; j++)
                    acc[i][j] += ra[i] * rb[j];
        }
        __syncthreads();
    }

    #pragma unroll
    for (int i = 0; i < 8; i++) {
        const int r = row0 + i * 16 + ty;
        #pragma unroll
        for (int j = 0; j < 8; j++) {
            const int c = col0 + j * 16 + tx;
            float v = acc[i][j] + bias[c];
            if (EPI == 1) v = gelu_exact(v);
            if (EPI == 2) v += res[(size_t)r * N + c];
            C[(size_t)r * N + c] = v;
        }
    }
}

// ---------------- flash attention ------------------------------------------
// grid (SQ/64, NH, BATCH), 256 threads. 4 threads per query (sub = lane&3),
// keys interleaved j = jj*4 + sub. smem pitch 65 -> conflict-free.
__global__ __launch_bounds__(256, 2) void attn_kernel(
    const float* __restrict__ Qg, const float* __restrict__ Kg,
    const float* __restrict__ Vg, const float* __restrict__ mask,
    float* __restrict__ O)
{
    extern __shared__ float sm[];
    float* Qs = sm;               // [64][65]
    float* Ks = sm + 64 * 65;     // [64][65]
    float* Vs = sm + 2 * 64 * 65; // [64][65]

    const int t  = threadIdx.x;
    const int q0 = blockIdx.x * 64;
    const int h  = blockIdx.y;
    const int b  = blockIdx.z;

    const int lr = t >> 2;          // loader row 0..63
    const int lc = (t & 3) * 16;    // loader col start
    const size_t base = (size_t)b * SQ * DM + (size_t)h * HD;

    // load + pre-scale Q tile (1/sqrt(64) = 0.125)
    {
        const float* src = Qg + base + (size_t)(q0 + lr) * DM + lc;
        #pragma unroll
        for (int i = 0; i < 16; i += 4) {
            float4 v = *(const float4*)(src + i);
            Qs[lr * 65 + lc + i + 0] = v.x * 0.125f;
            Qs[lr * 65 + lc + i + 1] = v.y * 0.125f;
            Qs[lr * 65 + lc + i + 2] = v.z * 0.125f;
            Qs[lr * 65 + lc + i + 3] = v.w * 0.125f;
        }
    }

    const int qi  = t >> 2;
    const int sub = t & 3;

    float m = -1e30f, l = 0.f;
    float acc[64];
    #pragma unroll
    for (int d = 0; d < 64; d++) acc[d] = 0.f;

    for (int kt = 0; kt < SQ; kt += 64) {
        __syncthreads();   // Q ready (iter 0); K/V consumers done (iter>0)
        {
            const float* ksrc = Kg + base + (size_t)(kt + lr) * DM + lc;
            const float* vsrc = Vg + base + (size_t)(kt + lr) * DM + lc;
            #pragma unroll
            for (int i = 0; i < 16; i += 4) {
                float4 kv = *(const float4*)(ksrc + i);
                Ks[lr * 65 + lc + i + 0] = kv.x;
                Ks[lr * 65 + lc + i + 1] = kv.y;
                Ks[lr * 65 + lc + i + 2] = kv.z;
                Ks[lr * 65 + lc + i + 3] = kv.w;
                float4 vv = *(const float4*)(vsrc + i);
                Vs[lr * 65 + lc + i + 0] = vv.x;
                Vs[lr * 65 + lc + i + 1] = vv.y;
                Vs[lr * 65 + lc + i + 2] = vv.z;
                Vs[lr * 65 + lc + i + 3] = vv.w;
            }
        }
        __syncthreads();

        // scores for this thread's 16 keys
        float s[16];
        #pragma unroll
        for (int jj = 0; jj < 16; jj++) s[jj] = 0.f;
        #pragma unroll
        for (int d = 0; d < 64; d++) {
            const float qv = Qs[qi * 65 + d];
            #pragma unroll
            for (int jj = 0; jj < 16; jj++)
                s[jj] += qv * Ks[(jj * 4 + sub) * 65 + d];
        }
        const float* mrow = mask + ((size_t)b * SQ + (q0 + qi)) * SQ + kt;
        #pragma unroll
        for (int jj = 0; jj < 16; jj++) s[jj] += mrow[jj * 4 + sub];

        // online softmax (group of 4 lanes per query)
        float tmax = s[0];
        #pragma unroll
        for (int jj = 1; jj < 16; jj++) tmax = fmaxf(tmax, s[jj]);
        tmax = fmaxf(tmax, __shfl_xor_sync(0xffffffffu, tmax, 1));
        tmax = fmaxf(tmax, __shfl_xor_sync(0xffffffffu, tmax, 2));
        const float m_new = fmaxf(m, tmax);
        const float scale = __expf(m - m_new);

        float lsum = 0.f;
        #pragma unroll
        for (int jj = 0; jj < 16; jj++) {
            const float p = __expf(s[jj] - m_new);
            s[jj] = p;
            lsum += p;
        }
        lsum += __shfl_xor_sync(0xffffffffu, lsum, 1);
        lsum += __shfl_xor_sync(0xffffffffu, lsum, 2);
        l = l * scale + lsum;
        m = m_new;

        #pragma unroll
        for (int d = 0; d < 64; d++) acc[d] *= scale;
        #pragma unroll
        for (int jj = 0; jj < 16; jj++) {
            const float p = s[jj];
            const float* vrow = &Vs[(jj * 4 + sub) * 65];
            #pragma unroll
            for (int d = 0; d < 64; d++) acc[d] += p * vrow[d];
        }
    }

    // combine partial sums across the 4 lanes of the query group
    #pragma unroll
    for (int d = 0; d < 64; d++) {
        acc[d] += __shfl_xor_sync(0xffffffffu, acc[d], 1);
        acc[d] += __shfl_xor_sync(0xffffffffu, acc[d], 2);
    }
    const float inv_l = 1.f / l;

    float* dst = O + base + (size_t)(q0 + qi) * DM + sub * 16;
    #pragma unroll
    for (int i = 0; i < 16; i += 4) {
        float4 o;
        o.x = acc[sub * 16 + i + 0] * inv_l;
        o.y = acc[sub * 16 + i + 1] * inv_l;
        o.z = acc[sub * 16 + i + 2] * inv_l;
        o.w = acc[sub * 16 + i + 3] * inv_l;
        *(float4*)(dst + i) = o;
    }
}

// ---------------- LayerNorm over last dim (512), one row per block ---------
__global__ __launch_bounds__(256) void ln_kernel(
    const float* __restrict__ X, const float* __restrict__ gam,
    const float* __restrict__ bet, float* __restrict__ O)
{
    __shared__ float s1[8], s2[8];
    const int row = blockIdx.x;
    const int t = threadIdx.x;
    const float* x = X + (size_t)row * DM;
    const float a = x[t];
    const float c = x[t + 256];

    float sum = a + c;
    float sq  = a * a + c * c;
    #pragma unroll
    for (int o = 16; o; o >>= 1) {
        sum += __shfl_xor_sync(0xffffffffu, sum, o);
        sq  += __shfl_xor_sync(0xffffffffu, sq,  o);
    }
    if ((t & 31) == 0) { s1[t >> 5] = sum; s2[t >> 5] = sq; }
    __syncthreads();
    sum = 0.f; sq = 0.f;
    #pragma unroll
    for (int i = 0; i < 8; i++) { sum += s1[i]; sq += s2[i]; }

    const float mu  = sum * (1.0f / DM);
    const float var = sq * (1.0f / DM) - mu * mu;
    const float inv = rsqrtf(var + 1e-12f);

    O[(size_t)row * DM + t]       = (a - mu) * inv * gam[t]       + bet[t];
    O[(size_t)row * DM + t + 256] = (c - mu) * inv * gam[t + 256] + bet[t + 256];
}

// ---------------- launch ----------------------------------------------------
extern "C" void kernel_launch(void* const* d_in, const int* in_sizes, int n_in,
                              void* d_out, int out_size)
{
    const float* x     = (const float*)d_in[0];
    const float* mask  = (const float*)d_in[1];
    const float* Wq    = (const float*)d_in[2];
    const float* bq    = (const float*)d_in[3];
    const float* Wk    = (const float*)d_in[4];
    const float* bk    = (const float*)d_in[5];
    const float* Wv    = (const float*)d_in[6];
    const float* bv    = (const float*)d_in[7];
    const float* Wo    = (const float*)d_in[8];
    const float* bo    = (const float*)d_in[9];
    const float* ln1g  = (const float*)d_in[10];
    const float* ln1b  = (const float*)d_in[11];
    const float* W1    = (const float*)d_in[12];
    const float* b1    = (const float*)d_in[13];
    const float* W2    = (const float*)d_in[14];
    const float* b2    = (const float*)d_in[15];
    const float* ln2g  = (const float*)d_in[16];
    const float* ln2b  = (const float*)d_in[17];
    float* out = (float*)d_out;

    float *Q, *K, *V, *Ctx, *T1, *A, *H, *T2;
    cudaGetSymbolAddress((void**)&Q,   g_Q);
    cudaGetSymbolAddress((void**)&K,   g_K);
    cudaGetSymbolAddress((void**)&V,   g_V);
    cudaGetSymbolAddress((void**)&Ctx, g_Ctx);
    cudaGetSymbolAddress((void**)&T1,  g_T1);
    cudaGetSymbolAddress((void**)&A,   g_A);
    cudaGetSymbolAddress((void**)&H,   g_H);
    cudaGetSymbolAddress((void**)&T2,  g_T2);

    const int attn_smem = 3 * 64 * 65 * (int)sizeof(float);  // 49920 B
    cudaFuncSetAttribute(attn_kernel, cudaFuncAttributeMaxDynamicSharedMemorySize,
                         attn_smem);

    dim3 thr(256);
    dim3 gDM(DM / BN, TOKENS / BM);    // (4, 128)
    dim3 gFF(DFF / BN, TOKENS / BM);   // (16, 128)

    // QKV projections
    sgemm_kernel<0><<<gDM, thr>>>(x, Wq, bq, nullptr, Q, TOKENS, DM, DM);
    sgemm_kernel<0><<<gDM, thr>>>(x, Wk, bk, nullptr, K, TOKENS, DM, DM);
    sgemm_kernel<0><<<gDM, thr>>>(x, Wv, bv, nullptr, V, TOKENS, DM, DM);

    // attention
    attn_kernel<<<dim3(SQ / 64, NH, BATCH), thr, attn_smem>>>(Q, K, V, mask, Ctx);

    // O projection + residual, then LN1
    sgemm_kernel<2><<<gDM, thr>>>(Ctx, Wo, bo, x, T1, TOKENS, DM, DM);
    ln_kernel<<<TOKENS, thr>>>(T1, ln1g, ln1b, A);

    // FFN
    sgemm_kernel<1><<<gFF, thr>>>(A, W1, b1, nullptr, H, TOKENS, DFF, DM);
    sgemm_kernel<2><<<gDM, thr>>>(H, W2, b2, A, T2, TOKENS, DM, DFF);
    ln_kernel<<<TOKENS, thr>>>(T2, ln2g, ln2b, out);
}

// round 4
// speedup vs baseline: 2.0629x; 2.0629x over previous
#include <cuda_runtime.h>
#include <math.h>
#include <stdint.h>

#define BATCH   32
#define SQ      512
#define DM      512
#define DFF     2048
#define NH      8
#define HD      64
#define TOKENS  (BATCH * SQ)   // 16384

// ---------------- scratch (device globals) ----------------------------------
__device__ float g_Q   [TOKENS * DM];
__device__ float g_K   [TOKENS * DM];
__device__ float g_V   [TOKENS * DM];
__device__ float g_Ctx [TOKENS * DM];
__device__ float g_T1  [TOKENS * DM];
__device__ float g_A   [TOKENS * DM];
__device__ float g_Art [TOKENS * DM];
__device__ float g_H   [TOKENS * DFF];
__device__ float g_T2  [TOKENS * DM];
__device__ float g_xrt [TOKENS * DM];
__device__ float g_Wq  [DM * DM];
__device__ float g_Wk  [DM * DM];
__device__ float g_Wv  [DM * DM];
__device__ float g_Wo  [DM * DM];
__device__ float g_W1  [DM * DFF];
__device__ float g_W2  [DFF * DM];

// ---------------- helpers ----------------------------------------------------
__device__ __forceinline__ uint32_t smem_u32(const void* p) {
    uint32_t a;
    asm("{ .reg .u64 t; cvta.to.shared.u64 t, %1; cvt.u32.u64 %0, t; }"
        : "=r"(a) : "l"(p));
    return a;
}
__device__ __forceinline__ float rna_tf32(float x) {
    float y;
    asm("cvt.rna.tf32.f32 %0, %1;" : "=f"(y) : "f"(x));
    return y;
}
__device__ __forceinline__ void cp_async16(uint32_t dst, const void* src) {
    asm volatile("cp.async.cg.shared.global [%0], [%1], 16;" :: "r"(dst), "l"(src));
}
__device__ __forceinline__ void cp_commit() {
    asm volatile("cp.async.commit_group;" ::: "memory");
}
template <int N> __device__ __forceinline__ void cp_wait() {
    asm volatile("cp.async.wait_group %0;" :: "n"(N) : "memory");
}
__device__ __forceinline__ void mma_tf32(float* d, const uint32_t* a,
                                         const uint32_t* b) {
    asm volatile(
        "mma.sync.aligned.m16n8k8.row.col.f32.tf32.tf32.f32 "
        "{%0,%1,%2,%3}, {%4,%5,%6,%7}, {%8,%9}, {%0,%1,%2,%3};"
        : "+f"(d[0]), "+f"(d[1]), "+f"(d[2]), "+f"(d[3])
        : "r"(a[0]), "r"(a[1]), "r"(a[2]), "r"(a[3]), "r"(b[0]), "r"(b[1]));
}
__device__ __forceinline__ float gelu_exact(float v) {
    return 0.5f * v * (1.0f + erff(v * 0.70710678118654752f));
}

// ---------------- tensor-core tf32 GEMM (mma.sync) ---------------------------
// C[M,N] = A[M,K] @ B[K,N] + bias.  EPI: 0=bias, 1=bias+gelu(->rna), 2=bias+res
// CTA 128x128, 256 thr, warp grid 2(M)x4(N), warp tile 64x32, BK=32, 2 stages.
#define APITCH 36          // floats; bank-conflict-free A fragment loads
#define BPITCH 136         // floats; bank-conflict-free B fragment loads
#define A_FLOATS (128 * APITCH)          // 4608
#define STAGE_FLOATS (A_FLOATS + 32 * BPITCH)   // 4608 + 4352 = 8960
#define GEMM_SMEM (2 * STAGE_FLOATS * 4)        // 71680 B

template <int EPI>
__global__ __launch_bounds__(256, 2) void gemm_mma(
    const float* __restrict__ A, const float* __restrict__ B,
    const float* __restrict__ bias, const float* __restrict__ res,
    float* __restrict__ C, int K, int N)
{
    extern __shared__ float sm[];
    const uint32_t sb = smem_u32(sm);
    const int tid  = threadIdx.x;
    const int lane = tid & 31, wid = tid >> 5;
    const int warpM = wid & 1;        // 0..1 -> 64 rows each
    const int warpN = wid >> 1;       // 0..3 -> 32 cols each
    const int gID = lane >> 2, t4 = lane & 3;
    const int row0 = blockIdx.y * 128;
    const int col0 = blockIdx.x * 128;

    const int NC = K / 32;

    auto load_chunk = [&](int c, int s) {
        const int k0 = c * 32;
        const uint32_t as = sb + (uint32_t)(s * STAGE_FLOATS) * 4;
        const uint32_t bs = as + A_FLOATS * 4;
        #pragma unroll
        for (int i = 0; i < 4; i++) {          // A tile 128x32
            int ch = tid + i * 256;
            int r = ch >> 3, q = (ch & 7) * 4;
            cp_async16(as + (uint32_t)(r * APITCH + q) * 4,
                       A + (size_t)(row0 + r) * K + k0 + q);
        }
        #pragma unroll
        for (int i = 0; i < 4; i++) {          // B tile 32x128
            int ch = tid + i * 256;
            int r = ch >> 5, c4 = (ch & 31) * 4;
            cp_async16(bs + (uint32_t)(r * BPITCH + c4) * 4,
                       B + (size_t)(k0 + r) * N + col0 + c4);
        }
    };

    load_chunk(0, 0); cp_commit();
    load_chunk(1, 1); cp_commit();

    float acc[4][4][4];
    #pragma unroll
    for (int i = 0; i < 4; i++)
        #pragma unroll
        for (int j = 0; j < 4; j++)
            #pragma unroll
            for (int e = 0; e < 4; e++) acc[i][j][e] = 0.f;

    for (int c = 0; c < NC; c++) {
        cp_wait<1>();
        __syncthreads();
        const float* as = sm + (c & 1) * STAGE_FLOATS;
        const float* bs = as + A_FLOATS;

        #pragma unroll
        for (int ks = 0; ks < 4; ks++) {
            const int k0 = ks * 8;
            uint32_t af[4][4], bf[4][2];
            #pragma unroll
            for (int am = 0; am < 4; am++) {
                const float* ap = as + (warpM * 64 + am * 16 + gID) * APITCH + k0 + t4;
                af[am][0] = __float_as_uint(ap[0]);
                af[am][1] = __float_as_uint(ap[8 * APITCH]);
                af[am][2] = __float_as_uint(ap[4]);
                af[am][3] = __float_as_uint(ap[8 * APITCH + 4]);
            }
            #pragma unroll
            for (int an = 0; an < 4; an++) {
                const float* bp = bs + (k0 + t4) * BPITCH + warpN * 32 + an * 8 + gID;
                bf[an][0] = __float_as_uint(bp[0]);
                bf[an][1] = __float_as_uint(bp[4 * BPITCH]);
            }
            #pragma unroll
            for (int am = 0; am < 4; am++)
                #pragma unroll
                for (int an = 0; an < 4; an++)
                    mma_tf32(acc[am][an], af[am], bf[an]);
        }
        __syncthreads();
        if (c + 2 < NC) load_chunk(c + 2, c & 1);
        cp_commit();
    }

    // epilogue: direct float2 stores
    #pragma unroll
    for (int am = 0; am < 4; am++) {
        const int rA = row0 + warpM * 64 + am * 16 + gID;
        #pragma unroll
        for (int half = 0; half < 2; half++) {
            const int r = rA + half * 8;
            #pragma unroll
            for (int an = 0; an < 4; an++) {
                const int cg = col0 + warpN * 32 + an * 8 + t4 * 2;
                float2 bv = *(const float2*)(bias + cg);
                float2 o;
                o.x = acc[am][an][half * 2 + 0] + bv.x;
                o.y = acc[am][an][half * 2 + 1] + bv.y;
                if (EPI == 1) {
                    o.x = rna_tf32(gelu_exact(o.x));
                    o.y = rna_tf32(gelu_exact(o.y));
                }
                if (EPI == 2) {
                    float2 rv = *(const float2*)(res + (size_t)r * N + cg);
                    o.x += rv.x; o.y += rv.y;
                }
                *(float2*)(C + (size_t)r * N + cg) = o;
            }
        }
    }
}

// ---------------- prep: elementwise tf32 rounding -----------------------------
__global__ __launch_bounds__(256) void round_rna_kernel(
    const float* __restrict__ in, float* __restrict__ out, int n4)
{
    int i = blockIdx.x * 256 + threadIdx.x;
    if (i < n4) {
        float4 v = ((const float4*)in)[i];
        v.x = rna_tf32(v.x); v.y = rna_tf32(v.y);
        v.z = rna_tf32(v.z); v.w = rna_tf32(v.w);
        ((float4*)out)[i] = v;
    }
}

// ---------------- flash attention (SIMT fp32, rna-rounded output) -------------
__global__ __launch_bounds__(256, 2) void attn_kernel(
    const float* __restrict__ Qg, const float* __restrict__ Kg,
    const float* __restrict__ Vg, const float* __restrict__ mask,
    float* __restrict__ O)
{
    extern __shared__ float sm[];
    float* Qs = sm;
    float* Ks = sm + 64 * 65;
    float* Vs = sm + 2 * 64 * 65;

    const int t  = threadIdx.x;
    const int q0 = blockIdx.x * 64;
    const int h  = blockIdx.y;
    const int b  = blockIdx.z;

    const int lr = t >> 2;
    const int lc = (t & 3) * 16;
    const size_t base = (size_t)b * SQ * DM + (size_t)h * HD;

    {
        const float* src = Qg + base + (size_t)(q0 + lr) * DM + lc;
        #pragma unroll
        for (int i = 0; i < 16; i += 4) {
            float4 v = *(const float4*)(src + i);
            Qs[lr * 65 + lc + i + 0] = v.x * 0.125f;
            Qs[lr * 65 + lc + i + 1] = v.y * 0.125f;
            Qs[lr * 65 + lc + i + 2] = v.z * 0.125f;
            Qs[lr * 65 + lc + i + 3] = v.w * 0.125f;
        }
    }

    const int qi  = t >> 2;
    const int sub = t & 3;

    float m = -1e30f, l = 0.f;
    float acc[64];
    #pragma unroll
    for (int d = 0; d < 64; d++) acc[d] = 0.f;

    for (int kt = 0; kt < SQ; kt += 64) {
        __syncthreads();
        {
            const float* ksrc = Kg + base + (size_t)(kt + lr) * DM + lc;
            const float* vsrc = Vg + base + (size_t)(kt + lr) * DM + lc;
            #pragma unroll
            for (int i = 0; i < 16; i += 4) {
                float4 kv = *(const float4*)(ksrc + i);
                Ks[lr * 65 + lc + i + 0] = kv.x;
                Ks[lr * 65 + lc + i + 1] = kv.y;
                Ks[lr * 65 + lc + i + 2] = kv.z;
                Ks[lr * 65 + lc + i + 3] = kv.w;
                float4 vv = *(const float4*)(vsrc + i);
                Vs[lr * 65 + lc + i + 0] = vv.x;
                Vs[lr * 65 + lc + i + 1] = vv.y;
                Vs[lr * 65 + lc + i + 2] = vv.z;
                Vs[lr * 65 + lc + i + 3] = vv.w;
            }
        }
        __syncthreads();

        float s[16];
        #pragma unroll
        for (int jj = 0; jj < 16; jj++) s[jj] = 0.f;
        #pragma unroll
        for (int d = 0; d < 64; d++) {
            const float qv = Qs[qi * 65 + d];
            #pragma unroll
            for (int jj = 0; jj < 16; jj++)
                s[jj] += qv * Ks[(jj * 4 + sub) * 65 + d];
        }
        const float* mrow = mask + ((size_t)b * SQ + (q0 + qi)) * SQ + kt;
        #pragma unroll
        for (int jj = 0; jj < 16; jj++) s[jj] += mrow[jj * 4 + sub];

        float tmax = s[0];
        #pragma unroll
        for (int jj = 1; jj < 16; jj++) tmax = fmaxf(tmax, s[jj]);
        tmax = fmaxf(tmax, __shfl_xor_sync(0xffffffffu, tmax, 1));
        tmax = fmaxf(tmax, __shfl_xor_sync(0xffffffffu, tmax, 2));
        const float m_new = fmaxf(m, tmax);
        const float scale = __expf(m - m_new);

        float lsum = 0.f;
        #pragma unroll
        for (int jj = 0; jj < 16; jj++) {
            const float p = __expf(s[jj] - m_new);
            s[jj] = p;
            lsum += p;
        }
        lsum += __shfl_xor_sync(0xffffffffu, lsum, 1);
        lsum += __shfl_xor_sync(0xffffffffu, lsum, 2);
        l = l * scale + lsum;
        m = m_new;

        #pragma unroll
        for (int d = 0; d < 64; d++) acc[d] *= scale;
        #pragma unroll
        for (int jj = 0; jj < 16; jj++) {
            const float p = s[jj];
            const float* vrow = &Vs[(jj * 4 + sub) * 65];
            #pragma unroll
            for (int d = 0; d < 64; d++) acc[d] += p * vrow[d];
        }
    }

    #pragma unroll
    for (int d = 0; d < 64; d++) {
        acc[d] += __shfl_xor_sync(0xffffffffu, acc[d], 1);
        acc[d] += __shfl_xor_sync(0xffffffffu, acc[d], 2);
    }
    const float inv_l = 1.f / l;

    float* dst = O + base + (size_t)(q0 + qi) * DM + sub * 16;
    #pragma unroll
    for (int i = 0; i < 16; i += 4) {
        float4 o;
        o.x = rna_tf32(acc[sub * 16 + i + 0] * inv_l);
        o.y = rna_tf32(acc[sub * 16 + i + 1] * inv_l);
        o.z = rna_tf32(acc[sub * 16 + i + 2] * inv_l);
        o.w = rna_tf32(acc[sub * 16 + i + 3] * inv_l);
        *(float4*)(dst + i) = o;
    }
}

// ---------------- LayerNorm (exact out + optional rounded copy) ---------------
template <bool RND>
__global__ __launch_bounds__(256) void ln_kernel(
    const float* __restrict__ X, const float* __restrict__ gam,
    const float* __restrict__ bet, float* __restrict__ O,
    float* __restrict__ Ort)
{
    __shared__ float s1[8], s2[8];
    const int row = blockIdx.x;
    const int t = threadIdx.x;
    const float* x = X + (size_t)row * DM;
    const float a = x[t];
    const float c = x[t + 256];

    float sum = a + c;
    float sq  = a * a + c * c;
    #pragma unroll
    for (int o = 16; o; o >>= 1) {
        sum += __shfl_xor_sync(0xffffffffu, sum, o);
        sq  += __shfl_xor_sync(0xffffffffu, sq,  o);
    }
    if ((t & 31) == 0) { s1[t >> 5] = sum; s2[t >> 5] = sq; }
    __syncthreads();
    sum = 0.f; sq = 0.f;
    #pragma unroll
    for (int i = 0; i < 8; i++) { sum += s1[i]; sq += s2[i]; }

    const float mu  = sum * (1.0f / DM);
    const float var = sq * (1.0f / DM) - mu * mu;
    const float inv = rsqrtf(var + 1e-12f);

    const float o0 = (a - mu) * inv * gam[t]       + bet[t];
    const float o1 = (c - mu) * inv * gam[t + 256] + bet[t + 256];
    O[(size_t)row * DM + t]       = o0;
    O[(size_t)row * DM + t + 256] = o1;
    if (RND) {
        Ort[(size_t)row * DM + t]       = rna_tf32(o0);
        Ort[(size_t)row * DM + t + 256] = rna_tf32(o1);
    }
}

// ---------------- launch -------------------------------------------------------
extern "C" void kernel_launch(void* const* d_in, const int* in_sizes, int n_in,
                              void* d_out, int out_size)
{
    const float* x    = (const float*)d_in[0];
    const float* mask = (const float*)d_in[1];
    const float* Wq   = (const float*)d_in[2];
    const float* bq   = (const float*)d_in[3];
    const float* Wk   = (const float*)d_in[4];
    const float* bk   = (const float*)d_in[5];
    const float* Wv   = (const float*)d_in[6];
    const float* bv   = (const float*)d_in[7];
    const float* Wo   = (const float*)d_in[8];
    const float* bo   = (const float*)d_in[9];
    const float* ln1g = (const float*)d_in[10];
    const float* ln1b = (const float*)d_in[11];
    const float* W1   = (const float*)d_in[12];
    const float* b1   = (const float*)d_in[13];
    const float* W2   = (const float*)d_in[14];
    const float* b2   = (const float*)d_in[15];
    const float* ln2g = (const float*)d_in[16];
    const float* ln2b = (const float*)d_in[17];
    float* out = (float*)d_out;

    float *Q, *K, *V, *Ctx, *T1, *A, *Art, *H, *T2, *xrt;
    float *rWq, *rWk, *rWv, *rWo, *rW1, *rW2;
    cudaGetSymbolAddress((void**)&Q,   g_Q);
    cudaGetSymbolAddress((void**)&K,   g_K);
    cudaGetSymbolAddress((void**)&V,   g_V);
    cudaGetSymbolAddress((void**)&Ctx, g_Ctx);
    cudaGetSymbolAddress((void**)&T1,  g_T1);
    cudaGetSymbolAddress((void**)&A,   g_A);
    cudaGetSymbolAddress((void**)&Art, g_Art);
    cudaGetSymbolAddress((void**)&H,   g_H);
    cudaGetSymbolAddress((void**)&T2,  g_T2);
    cudaGetSymbolAddress((void**)&xrt, g_xrt);
    cudaGetSymbolAddress((void**)&rWq, g_Wq);
    cudaGetSymbolAddress((void**)&rWk, g_Wk);
    cudaGetSymbolAddress((void**)&rWv, g_Wv);
    cudaGetSymbolAddress((void**)&rWo, g_Wo);
    cudaGetSymbolAddress((void**)&rW1, g_W1);
    cudaGetSymbolAddress((void**)&rW2, g_W2);

    cudaFuncSetAttribute(gemm_mma<0>, cudaFuncAttributeMaxDynamicSharedMemorySize, GEMM_SMEM);
    cudaFuncSetAttribute(gemm_mma<1>, cudaFuncAttributeMaxDynamicSharedMemorySize, GEMM_SMEM);
    cudaFuncSetAttribute(gemm_mma<2>, cudaFuncAttributeMaxDynamicSharedMemorySize, GEMM_SMEM);
    cudaFuncSetAttribute(attn_kernel, cudaFuncAttributeMaxDynamicSharedMemorySize,
                         3 * 64 * 65 * (int)sizeof(float));

    dim3 thr(256);

    // prep: tf32-round activations and weights
    round_rna_kernel<<<TOKENS * DM / 4 / 256, thr>>>(x, xrt, TOKENS * DM / 4);
    round_rna_kernel<<<DM * DM / 4 / 256, thr>>>(Wq, rWq, DM * DM / 4);
    round_rna_kernel<<<DM * DM / 4 / 256, thr>>>(Wk, rWk, DM * DM / 4);
    round_rna_kernel<<<DM * DM / 4 / 256, thr>>>(Wv, rWv, DM * DM / 4);
    round_rna_kernel<<<DM * DM / 4 / 256, thr>>>(Wo, rWo, DM * DM / 4);
    round_rna_kernel<<<DM * DFF / 4 / 256, thr>>>(W1, rW1, DM * DFF / 4);
    round_rna_kernel<<<DFF * DM / 4 / 256, thr>>>(W2, rW2, DFF * DM / 4);

    const dim3 gDM(DM / 128, TOKENS / 128);    // (4, 128)
    const dim3 gFF(DFF / 128, TOKENS / 128);   // (16, 128)

    // QKV projections (tensor cores)
    gemm_mma<0><<<gDM, thr, GEMM_SMEM>>>(xrt, rWq, bq, nullptr, Q, DM, DM);
    gemm_mma<0><<<gDM, thr, GEMM_SMEM>>>(xrt, rWk, bk, nullptr, K, DM, DM);
    gemm_mma<0><<<gDM, thr, GEMM_SMEM>>>(xrt, rWv, bv, nullptr, V, DM, DM);

    // attention (fp32 SIMT)
    attn_kernel<<<dim3(SQ / 64, NH, BATCH), thr, 3 * 64 * 65 * (int)sizeof(float)>>>(
        Q, K, V, mask, Ctx);

    // O projection + residual(x), LN1
    gemm_mma<2><<<gDM, thr, GEMM_SMEM>>>(Ctx, rWo, bo, x, T1, DM, DM);
    ln_kernel<true><<<TOKENS, thr>>>(T1, ln1g, ln1b, A, Art);

    // FFN
    gemm_mma<1><<<gFF, thr, GEMM_SMEM>>>(Art, rW1, b1, nullptr, H, DM, DFF);
    gemm_mma<2><<<gDM, thr, GEMM_SMEM>>>(H, rW2, b2, A, T2, DFF, DM);
    ln_kernel<false><<<TOKENS, thr>>>(T2, ln2g, ln2b, out, nullptr);
}

// round 5
// speedup vs baseline: 4.0666x; 1.9713x over previous
#include <cuda_runtime.h>
#include <math.h>
#include <stdint.h>

#define BATCH   32
#define SQ      512
#define DM      512
#define DFF     2048
#define NH      8
#define HD      64
#define TOKENS  (BATCH * SQ)   // 16384
#define QKVN    1536

// ---------------- scratch (device globals) ----------------------------------
__device__ float g_QKV [TOKENS * QKVN];
__device__ float g_Ctx [TOKENS * DM];
__device__ float g_T1  [TOKENS * DM];
__device__ float g_A   [TOKENS * DM];
__device__ float g_Art [TOKENS * DM];
__device__ float g_H   [TOKENS * DFF];
__device__ float g_T2  [TOKENS * DM];
__device__ float g_xrt [TOKENS * DM];
__device__ float g_Wqkv[DM * QKVN];
__device__ float g_bqkv[QKVN];
__device__ float g_Wo  [DM * DM];
__device__ float g_W1  [DM * DFF];
__device__ float g_W2  [DFF * DM];

// ---------------- helpers ----------------------------------------------------
__device__ __forceinline__ uint32_t smem_u32(const void* p) {
    uint32_t a;
    asm("{ .reg .u64 t; cvta.to.shared.u64 t, %1; cvt.u32.u64 %0, t; }"
        : "=r"(a) : "l"(p));
    return a;
}
__device__ __forceinline__ float rna_tf32(float x) {
    float y;
    asm("cvt.rna.tf32.f32 %0, %1;" : "=f"(y) : "f"(x));
    return y;
}
__device__ __forceinline__ void cp_async16(uint32_t dst, const void* src) {
    asm volatile("cp.async.cg.shared.global [%0], [%1], 16;" :: "r"(dst), "l"(src));
}
__device__ __forceinline__ void cp_commit() {
    asm volatile("cp.async.commit_group;" ::: "memory");
}
template <int N> __device__ __forceinline__ void cp_wait() {
    asm volatile("cp.async.wait_group %0;" :: "n"(N) : "memory");
}
__device__ __forceinline__ void mma_tf32(float* d, const uint32_t* a,
                                         const uint32_t* b) {
    asm volatile(
        "mma.sync.aligned.m16n8k8.row.col.f32.tf32.tf32.f32 "
        "{%0,%1,%2,%3}, {%4,%5,%6,%7}, {%8,%9}, {%0,%1,%2,%3};"
        : "+f"(d[0]), "+f"(d[1]), "+f"(d[2]), "+f"(d[3])
        : "r"(a[0]), "r"(a[1]), "r"(a[2]), "r"(a[3]), "r"(b[0]), "r"(b[1]));
}
__device__ __forceinline__ float gelu_exact(float v) {
    return 0.5f * v * (1.0f + erff(v * 0.70710678118654752f));
}

// ---------------- tensor-core tf32 GEMM (mma.sync) ---------------------------
// C[M,N] = A[M,K] @ B[K,N] + bias.
// EPI: 0=bias, 1=bias+gelu(->rna), 2=bias+res, 3=bias->rna
#define APITCH 36
#define BPITCH 136
#define A_FLOATS (128 * APITCH)
#define STAGE_FLOATS (A_FLOATS + 32 * BPITCH)
#define GEMM_SMEM (2 * STAGE_FLOATS * 4)

template <int EPI>
__global__ __launch_bounds__(256, 2) void gemm_mma(
    const float* __restrict__ A, const float* __restrict__ B,
    const float* __restrict__ bias, const float* __restrict__ res,
    float* __restrict__ C, int K, int N)
{
    extern __shared__ float sm[];
    const uint32_t sb = smem_u32(sm);
    const int tid  = threadIdx.x;
    const int lane = tid & 31, wid = tid >> 5;
    const int warpM = wid & 1;
    const int warpN = wid >> 1;
    const int gID = lane >> 2, t4 = lane & 3;
    const int row0 = blockIdx.y * 128;
    const int col0 = blockIdx.x * 128;

    const int NC = K / 32;

    auto load_chunk = [&](int c, int s) {
        const int k0 = c * 32;
        const uint32_t as = sb + (uint32_t)(s * STAGE_FLOATS) * 4;
        const uint32_t bs = as + A_FLOATS * 4;
        #pragma unroll
        for (int i = 0; i < 4; i++) {
            int ch = tid + i * 256;
            int r = ch >> 3, q = (ch & 7) * 4;
            cp_async16(as + (uint32_t)(r * APITCH + q) * 4,
                       A + (size_t)(row0 + r) * K + k0 + q);
        }
        #pragma unroll
        for (int i = 0; i < 4; i++) {
            int ch = tid + i * 256;
            int r = ch >> 5, c4 = (ch & 31) * 4;
            cp_async16(bs + (uint32_t)(r * BPITCH + c4) * 4,
                       B + (size_t)(k0 + r) * N + col0 + c4);
        }
    };

    load_chunk(0, 0); cp_commit();
    load_chunk(1, 1); cp_commit();

    float acc[4][4][4];
    #pragma unroll
    for (int i = 0; i < 4; i++)
        #pragma unroll
        for (int j = 0; j < 4; j++)
            #pragma unroll
            for (int e = 0; e < 4; e++) acc[i][j][e] = 0.f;

    for (int c = 0; c < NC; c++) {
        cp_wait<1>();
        __syncthreads();
        const float* as = sm + (c & 1) * STAGE_FLOATS;
        const float* bs = as + A_FLOATS;

        #pragma unroll
        for (int ks = 0; ks < 4; ks++) {
            const int k0 = ks * 8;
            uint32_t af[4][4], bf[4][2];
            #pragma unroll
            for (int am = 0; am < 4; am++) {
                const float* ap = as + (warpM * 64 + am * 16 + gID) * APITCH + k0 + t4;
                af[am][0] = __float_as_uint(ap[0]);
                af[am][1] = __float_as_uint(ap[8 * APITCH]);
                af[am][2] = __float_as_uint(ap[4]);
                af[am][3] = __float_as_uint(ap[8 * APITCH + 4]);
            }
            #pragma unroll
            for (int an = 0; an < 4; an++) {
                const float* bp = bs + (k0 + t4) * BPITCH + warpN * 32 + an * 8 + gID;
                bf[an][0] = __float_as_uint(bp[0]);
                bf[an][1] = __float_as_uint(bp[4 * BPITCH]);
            }
            #pragma unroll
            for (int am = 0; am < 4; am++)
                #pragma unroll
                for (int an = 0; an < 4; an++)
                    mma_tf32(acc[am][an], af[am], bf[an]);
        }
        __syncthreads();
        if (c + 2 < NC) load_chunk(c + 2, c & 1);
        cp_commit();
    }

    #pragma unroll
    for (int am = 0; am < 4; am++) {
        const int rA = row0 + warpM * 64 + am * 16 + gID;
        #pragma unroll
        for (int half = 0; half < 2; half++) {
            const int r = rA + half * 8;
            #pragma unroll
            for (int an = 0; an < 4; an++) {
                const int cg = col0 + warpN * 32 + an * 8 + t4 * 2;
                float2 bv = *(const float2*)(bias + cg);
                float2 o;
                o.x = acc[am][an][half * 2 + 0] + bv.x;
                o.y = acc[am][an][half * 2 + 1] + bv.y;
                if (EPI == 1) {
                    o.x = rna_tf32(gelu_exact(o.x));
                    o.y = rna_tf32(gelu_exact(o.y));
                }
                if (EPI == 2) {
                    float2 rv = *(const float2*)(res + (size_t)r * N + cg);
                    o.x += rv.x; o.y += rv.y;
                }
                if (EPI == 3) {
                    o.x = rna_tf32(o.x);
                    o.y = rna_tf32(o.y);
                }
                *(float2*)(C + (size_t)r * N + cg) = o;
            }
        }
    }
}

// ---------------- prep kernels -------------------------------------------------
__global__ __launch_bounds__(256) void round_rna_kernel(
    const float* __restrict__ in, float* __restrict__ out, int n4)
{
    int i = blockIdx.x * 256 + threadIdx.x;
    if (i < n4) {
        float4 v = ((const float4*)in)[i];
        v.x = rna_tf32(v.x); v.y = rna_tf32(v.y);
        v.z = rna_tf32(v.z); v.w = rna_tf32(v.w);
        ((float4*)out)[i] = v;
    }
}

// scatter a [512x512] weight (rounded) into a [512x1536] fused buffer
__global__ __launch_bounds__(256) void round_scatter_kernel(
    const float* __restrict__ in, float* __restrict__ out, int n4)
{
    int i = blockIdx.x * 256 + threadIdx.x;
    if (i < n4) {
        int r = i >> 7;              // 128 float4 per row (512 cols)
        int c4 = (i & 127) * 4;
        float4 v = ((const float4*)in)[i];
        v.x = rna_tf32(v.x); v.y = rna_tf32(v.y);
        v.z = rna_tf32(v.z); v.w = rna_tf32(v.w);
        *(float4*)(out + (size_t)r * QKVN + c4) = v;
    }
}

// ---------------- tensor-core flash attention ---------------------------------
// grid (SQ/64, NH, BATCH), 128 threads (4 warps x 16 queries each).
// Ks stored transposed [dim][key] (pitch 72), Vs [key][dim] (pitch 72),
// Qs/Ms pitch 68. QK^T and P@V on mma.sync tf32; P->A frag via shfl.
#define AQP 68
#define AKP 72
#define ATTN_SMEM ((2 * 64 * AQP + 2 * 64 * AKP) * 4)   // 71680 B

__global__ __launch_bounds__(128, 3) void attn_mma(
    const float* __restrict__ QKV, const float* __restrict__ mask,
    float* __restrict__ Ctx)
{
    extern __shared__ float sm[];
    float* Qs = sm;                   // [64][68]
    float* Ks = sm + 64 * AQP;        // [64][72]  (dim-major!)
    float* Vs = Ks + 64 * AKP;        // [64][72]
    float* Ms = Vs + 64 * AKP;        // [64][68]
    const uint32_t qs_u = smem_u32(Qs);
    const uint32_t vs_u = smem_u32(Vs);
    const uint32_t ms_u = smem_u32(Ms);

    const int tid  = threadIdx.x;
    const int lane = tid & 31, w = tid >> 5;
    const int gID = lane >> 2, t4 = lane & 3;
    const int q0 = blockIdx.x * 64;
    const int h = blockIdx.y, b = blockIdx.z;
    const size_t tok0 = (size_t)b * SQ;
    const int qw = w * 16;

    // load Q tile once (cols 0..63 of pitch-68 rows)
    {
        const float* src = QKV + (tok0 + q0) * QKVN + h * HD;
        #pragma unroll
        for (int j = 0; j < 8; j++) {
            int id = tid + j * 128;
            int r = id >> 4, c = (id & 15) * 4;
            cp_async16(qs_u + (uint32_t)(r * AQP + c) * 4, src + (size_t)r * QKVN + c);
        }
        cp_commit();
    }

    float s[8][4], o[8][4];
    float m0 = -1e30f, m1 = -1e30f, l0 = 0.f, l1 = 0.f;
    #pragma unroll
    for (int j = 0; j < 8; j++)
        #pragma unroll
        for (int e = 0; e < 4; e++) o[j][e] = 0.f;

    for (int kt = 0; kt < SQ / 64; kt++) {
        const int k0g = kt * 64;
        // V + mask via cp.async
        const float* vsrc = QKV + (tok0 + k0g) * QKVN + 2 * DM + h * HD;
        #pragma unroll
        for (int j = 0; j < 8; j++) {
            int id = tid + j * 128;
            int r = id >> 4, c = (id & 15) * 4;
            cp_async16(vs_u + (uint32_t)(r * AKP + c) * 4, vsrc + (size_t)r * QKVN + c);
        }
        const float* msrc = mask + ((size_t)b * SQ + q0) * SQ + k0g;
        #pragma unroll
        for (int j = 0; j < 8; j++) {
            int id = tid + j * 128;
            int r = id >> 4, c = (id & 15) * 4;
            cp_async16(ms_u + (uint32_t)(r * AQP + c) * 4, msrc + (size_t)r * SQ + c);
        }
        cp_commit();
        // K tile: LDG + transposed STS -> Ks[dim][key]
        {
            const int r = tid & 63, ch = tid >> 6;   // ch in {0,1}: 32 dims each
            const float* ksrc = QKV + (tok0 + k0g + r) * QKVN + DM + h * HD + ch * 32;
            #pragma unroll
            for (int j = 0; j < 8; j++) {
                float4 kv = *(const float4*)(ksrc + j * 4);
                Ks[(ch * 32 + j * 4 + 0) * AKP + r] = kv.x;
                Ks[(ch * 32 + j * 4 + 1) * AKP + r] = kv.y;
                Ks[(ch * 32 + j * 4 + 2) * AKP + r] = kv.z;
                Ks[(ch * 32 + j * 4 + 3) * AKP + r] = kv.w;
            }
        }
        cp_wait<0>();
        __syncthreads();

        // ---- scores = Q @ K^T ----
        #pragma unroll
        for (int j = 0; j < 8; j++)
            #pragma unroll
            for (int e = 0; e < 4; e++) s[j][e] = 0.f;
        #pragma unroll
        for (int c = 0; c < 8; c++) {
            uint32_t a[4];
            const float* ap = Qs + (qw + gID) * AQP + c * 8 + t4;
            a[0] = __float_as_uint(ap[0]);
            a[1] = __float_as_uint(ap[8 * AQP]);
            a[2] = __float_as_uint(ap[4]);
            a[3] = __float_as_uint(ap[8 * AQP + 4]);
            #pragma unroll
            for (int an = 0; an < 8; an++) {
                uint32_t bfr[2];
                const float* bp = Ks + (c * 8 + t4) * AKP + an * 8 + gID;
                bfr[0] = __float_as_uint(bp[0]);
                bfr[1] = __float_as_uint(bp[4 * AKP]);
                mma_tf32(s[an], a, bfr);
            }
        }

        // ---- scale + mask + online softmax ----
        float rmax0 = -1e30f, rmax1 = -1e30f;
        #pragma unroll
        for (int j = 0; j < 8; j++) {
            const float* mr0 = Ms + (qw + gID) * AQP + j * 8 + t4 * 2;
            const float* mr1 = mr0 + 8 * AQP;
            s[j][0] = s[j][0] * 0.125f + mr0[0];
            s[j][1] = s[j][1] * 0.125f + mr0[1];
            s[j][2] = s[j][2] * 0.125f + mr1[0];
            s[j][3] = s[j][3] * 0.125f + mr1[1];
            rmax0 = fmaxf(rmax0, fmaxf(s[j][0], s[j][1]));
            rmax1 = fmaxf(rmax1, fmaxf(s[j][2], s[j][3]));
        }
        rmax0 = fmaxf(rmax0, __shfl_xor_sync(0xffffffffu, rmax0, 1));
        rmax0 = fmaxf(rmax0, __shfl_xor_sync(0xffffffffu, rmax0, 2));
        rmax1 = fmaxf(rmax1, __shfl_xor_sync(0xffffffffu, rmax1, 1));
        rmax1 = fmaxf(rmax1, __shfl_xor_sync(0xffffffffu, rmax1, 2));
        const float mn0 = fmaxf(m0, rmax0), mn1 = fmaxf(m1, rmax1);
        const float sc0 = __expf(m0 - mn0), sc1 = __expf(m1 - mn1);
        m0 = mn0; m1 = mn1;

        float ls0 = 0.f, ls1 = 0.f;
        #pragma unroll
        for (int j = 0; j < 8; j++) {
            float p0 = __expf(s[j][0] - mn0);
            float p1 = __expf(s[j][1] - mn0);
            float p2 = __expf(s[j][2] - mn1);
            float p3 = __expf(s[j][3] - mn1);
            ls0 += p0 + p1; ls1 += p2 + p3;
            s[j][0] = rna_tf32(p0); s[j][1] = rna_tf32(p1);
            s[j][2] = rna_tf32(p2); s[j][3] = rna_tf32(p3);
        }
        ls0 += __shfl_xor_sync(0xffffffffu, ls0, 1);
        ls0 += __shfl_xor_sync(0xffffffffu, ls0, 2);
        ls1 += __shfl_xor_sync(0xffffffffu, ls1, 1);
        ls1 += __shfl_xor_sync(0xffffffffu, ls1, 2);
        l0 = l0 * sc0 + ls0;
        l1 = l1 * sc1 + ls1;
        #pragma unroll
        for (int nd = 0; nd < 8; nd++) {
            o[nd][0] *= sc0; o[nd][1] *= sc0;
            o[nd][2] *= sc1; o[nd][3] *= sc1;
        }

        // ---- ctx += P @ V  (P->A fragment via shfl) ----
        const int tc = t4 >> 1, e = t4 & 1;
        const int s0l = gID * 4 + tc, s2l = s0l + 2;
        #pragma unroll
        for (int j = 0; j < 8; j++) {
            uint32_t a[4];
            float x0, x1;
            x0 = __shfl_sync(0xffffffffu, s[j][0], s0l);
            x1 = __shfl_sync(0xffffffffu, s[j][1], s0l);
            a[0] = __float_as_uint(e ? x1 : x0);
            x0 = __shfl_sync(0xffffffffu, s[j][2], s0l);
            x1 = __shfl_sync(0xffffffffu, s[j][3], s0l);
            a[1] = __float_as_uint(e ? x1 : x0);
            x0 = __shfl_sync(0xffffffffu, s[j][0], s2l);
            x1 = __shfl_sync(0xffffffffu, s[j][1], s2l);
            a[2] = __float_as_uint(e ? x1 : x0);
            x0 = __shfl_sync(0xffffffffu, s[j][2], s2l);
            x1 = __shfl_sync(0xffffffffu, s[j][3], s2l);
            a[3] = __float_as_uint(e ? x1 : x0);
            #pragma unroll
            for (int nd = 0; nd < 8; nd++) {
                uint32_t bfr[2];
                const float* bp = Vs + (j * 8 + t4) * AKP + nd * 8 + gID;
                bfr[0] = __float_as_uint(bp[0]);
                bfr[1] = __float_as_uint(bp[4 * AKP]);
                mma_tf32(o[nd], a, bfr);
            }
        }
        __syncthreads();
    }

    // ---- epilogue: normalize + rna-round + store ----
    const float il0 = 1.f / l0, il1 = 1.f / l1;
    float* dst0 = Ctx + (tok0 + q0 + qw + gID) * DM + h * HD;
    float* dst1 = dst0 + 8 * DM;
    #pragma unroll
    for (int nd = 0; nd < 8; nd++) {
        float2 v0, v1;
        v0.x = rna_tf32(o[nd][0] * il0);
        v0.y = rna_tf32(o[nd][1] * il0);
        v1.x = rna_tf32(o[nd][2] * il1);
        v1.y = rna_tf32(o[nd][3] * il1);
        *(float2*)(dst0 + nd * 8 + t4 * 2) = v0;
        *(float2*)(dst1 + nd * 8 + t4 * 2) = v1;
    }
}

// ---------------- LayerNorm (exact out + optional rounded copy) ---------------
template <bool RND>
__global__ __launch_bounds__(256) void ln_kernel(
    const float* __restrict__ X, const float* __restrict__ gam,
    const float* __restrict__ bet, float* __restrict__ O,
    float* __restrict__ Ort)
{
    __shared__ float s1[8], s2[8];
    const int row = blockIdx.x;
    const int t = threadIdx.x;
    const float* x = X + (size_t)row * DM;
    const float a = x[t];
    const float c = x[t + 256];

    float sum = a + c;
    float sq  = a * a + c * c;
    #pragma unroll
    for (int o = 16; o; o >>= 1) {
        sum += __shfl_xor_sync(0xffffffffu, sum, o);
        sq  += __shfl_xor_sync(0xffffffffu, sq,  o);
    }
    if ((t & 31) == 0) { s1[t >> 5] = sum; s2[t >> 5] = sq; }
    __syncthreads();
    sum = 0.f; sq = 0.f;
    #pragma unroll
    for (int i = 0; i < 8; i++) { sum += s1[i]; sq += s2[i]; }

    const float mu  = sum * (1.0f / DM);
    const float var = sq * (1.0f / DM) - mu * mu;
    const float inv = rsqrtf(var + 1e-12f);

    const float o0 = (a - mu) * inv * gam[t]       + bet[t];
    const float o1 = (c - mu) * inv * gam[t + 256] + bet[t + 256];
    O[(size_t)row * DM + t]       = o0;
    O[(size_t)row * DM + t + 256] = o1;
    if (RND) {
        Ort[(size_t)row * DM + t]       = rna_tf32(o0);
        Ort[(size_t)row * DM + t + 256] = rna_tf32(o1);
    }
}

// ---------------- launch -------------------------------------------------------
extern "C" void kernel_launch(void* const* d_in, const int* in_sizes, int n_in,
                              void* d_out, int out_size)
{
    const float* x    = (const float*)d_in[0];
    const float* mask = (const float*)d_in[1];
    const float* Wq   = (const float*)d_in[2];
    const float* bq   = (const float*)d_in[3];
    const float* Wk   = (const float*)d_in[4];
    const float* bk   = (const float*)d_in[5];
    const float* Wv   = (const float*)d_in[6];
    const float* bv   = (const float*)d_in[7];
    const float* Wo   = (const float*)d_in[8];
    const float* bo   = (const float*)d_in[9];
    const float* ln1g = (const float*)d_in[10];
    const float* ln1b = (const float*)d_in[11];
    const float* W1   = (const float*)d_in[12];
    const float* b1   = (const float*)d_in[13];
    const float* W2   = (const float*)d_in[14];
    const float* b2   = (const float*)d_in[15];
    const float* ln2g = (const float*)d_in[16];
    const float* ln2b = (const float*)d_in[17];
    float* out = (float*)d_out;

    float *QKV, *Ctx, *T1, *A, *Art, *H, *T2, *xrt;
    float *Wqkv, *bqkv, *rWo, *rW1, *rW2;
    cudaGetSymbolAddress((void**)&QKV,  g_QKV);
    cudaGetSymbolAddress((void**)&Ctx,  g_Ctx);
    cudaGetSymbolAddress((void**)&T1,   g_T1);
    cudaGetSymbolAddress((void**)&A,    g_A);
    cudaGetSymbolAddress((void**)&Art,  g_Art);
    cudaGetSymbolAddress((void**)&H,    g_H);
    cudaGetSymbolAddress((void**)&T2,   g_T2);
    cudaGetSymbolAddress((void**)&xrt,  g_xrt);
    cudaGetSymbolAddress((void**)&Wqkv, g_Wqkv);
    cudaGetSymbolAddress((void**)&bqkv, g_bqkv);
    cudaGetSymbolAddress((void**)&rWo,  g_Wo);
    cudaGetSymbolAddress((void**)&rW1,  g_W1);
    cudaGetSymbolAddress((void**)&rW2,  g_W2);

    cudaFuncSetAttribute(gemm_mma<0>, cudaFuncAttributeMaxDynamicSharedMemorySize, GEMM_SMEM);
    cudaFuncSetAttribute(gemm_mma<1>, cudaFuncAttributeMaxDynamicSharedMemorySize, GEMM_SMEM);
    cudaFuncSetAttribute(gemm_mma<2>, cudaFuncAttributeMaxDynamicSharedMemorySize, GEMM_SMEM);
    cudaFuncSetAttribute(gemm_mma<3>, cudaFuncAttributeMaxDynamicSharedMemorySize, GEMM_SMEM);
    cudaFuncSetAttribute(attn_mma, cudaFuncAttributeMaxDynamicSharedMemorySize, ATTN_SMEM);

    dim3 thr(256);

    // prep: round activations + weights (QKV weights scattered into fused buffer)
    round_rna_kernel<<<TOKENS * DM / 4 / 256, thr>>>(x, xrt, TOKENS * DM / 4);
    round_scatter_kernel<<<DM * DM / 4 / 256, thr>>>(Wq, Wqkv + 0 * DM, DM * DM / 4);
    round_scatter_kernel<<<DM * DM / 4 / 256, thr>>>(Wk, Wqkv + 1 * DM, DM * DM / 4);
    round_scatter_kernel<<<DM * DM / 4 / 256, thr>>>(Wv, Wqkv + 2 * DM, DM * DM / 4);
    round_rna_kernel<<<DM * DM / 4 / 256, thr>>>(Wo, rWo, DM * DM / 4);
    round_rna_kernel<<<DM * DFF / 4 / 256, thr>>>(W1, rW1, DM * DFF / 4);
    round_rna_kernel<<<DFF * DM / 4 / 256, thr>>>(W2, rW2, DFF * DM / 4);
    cudaMemcpyAsync(bqkv + 0 * DM, bq, DM * sizeof(float), cudaMemcpyDeviceToDevice);
    cudaMemcpyAsync(bqkv + 1 * DM, bk, DM * sizeof(float), cudaMemcpyDeviceToDevice);
    cudaMemcpyAsync(bqkv + 2 * DM, bv, DM * sizeof(float), cudaMemcpyDeviceToDevice);

    // fused QKV projection (rna-rounded output for attention MMA operands)
    gemm_mma<3><<<dim3(QKVN / 128, TOKENS / 128), thr, GEMM_SMEM>>>(
        xrt, Wqkv, bqkv, nullptr, QKV, DM, QKVN);

    // tensor-core flash attention
    attn_mma<<<dim3(SQ / 64, NH, BATCH), dim3(128), ATTN_SMEM>>>(QKV, mask, Ctx);

    // O projection + residual(x), LN1
    gemm_mma<2><<<dim3(DM / 128, TOKENS / 128), thr, GEMM_SMEM>>>(
        Ctx, rWo, bo, x, T1, DM, DM);
    ln_kernel<true><<<TOKENS, thr>>>(T1, ln1g, ln1b, A, Art);

    // FFN
    gemm_mma<1><<<dim3(DFF / 128, TOKENS / 128), thr, GEMM_SMEM>>>(
        Art, rW1, b1, nullptr, H, DM, DFF);
    gemm_mma<2><<<dim3(DM / 128, TOKENS / 128), thr, GEMM_SMEM>>>(
        H, rW2, b2, A, T2, DFF, DM);
    ln_kernel<false><<<TOKENS, thr>>>(T2, ln2g, ln2b, out, nullptr);
}

// round 6
// speedup vs baseline: 7.0830x; 1.7418x over previous
#include <cuda_runtime.h>
#include <cuda_fp16.h>
#include <math.h>
#include <stdint.h>

#define BATCH   32
#define SQ      512
#define DM      512
#define DFF     2048
#define NH      8
#define HD      64
#define TOKENS  (BATCH * SQ)   // 16384
#define QKVN    1536

// ---------------- scratch (device globals) ----------------------------------
__device__ __half g_xh   [TOKENS * DM];
__device__ __half g_QKV  [TOKENS * QKVN];
__device__ __half g_Ctx  [TOKENS * DM];
__device__ __half g_Ahf  [TOKENS * DM];
__device__ __half g_H    [TOKENS * DFF];
__device__ float  g_T1   [TOKENS * DM];
__device__ float  g_A    [TOKENS * DM];
__device__ float  g_T2   [TOKENS * DM];
__device__ __half g_Wqkvt[QKVN * DM];
__device__ __half g_Wot  [DM * DM];
__device__ __half g_W1t  [DFF * DM];
__device__ __half g_W2t  [DM * DFF];
__device__ float  g_bqkv [QKVN];

// ---------------- helpers ----------------------------------------------------
__device__ __forceinline__ uint32_t smem_u32(const void* p) {
    uint32_t a;
    asm("{ .reg .u64 t; cvta.to.shared.u64 t, %1; cvt.u32.u64 %0, t; }"
        : "=r"(a) : "l"(p));
    return a;
}
__device__ __forceinline__ void cp_async16(uint32_t dst, const void* src) {
    asm volatile("cp.async.cg.shared.global [%0], [%1], 16;" :: "r"(dst), "l"(src));
}
__device__ __forceinline__ void cp_commit() {
    asm volatile("cp.async.commit_group;" ::: "memory");
}
template <int N> __device__ __forceinline__ void cp_wait() {
    asm volatile("cp.async.wait_group %0;" :: "n"(N) : "memory");
}
__device__ __forceinline__ void ldsm_x4(uint32_t* r, uint32_t addr) {
    asm volatile("ldmatrix.sync.aligned.m8n8.x4.shared.b16 {%0,%1,%2,%3}, [%4];"
        : "=r"(r[0]), "=r"(r[1]), "=r"(r[2]), "=r"(r[3]) : "r"(addr));
}
__device__ __forceinline__ void ldsm_x4_t(uint32_t* r, uint32_t addr) {
    asm volatile("ldmatrix.sync.aligned.m8n8.x4.trans.shared.b16 {%0,%1,%2,%3}, [%4];"
        : "=r"(r[0]), "=r"(r[1]), "=r"(r[2]), "=r"(r[3]) : "r"(addr));
}
__device__ __forceinline__ void mma_f16(float* d, const uint32_t* a,
                                        const uint32_t* b) {
    asm volatile(
        "mma.sync.aligned.m16n8k16.row.col.f32.f16.f16.f32 "
        "{%0,%1,%2,%3}, {%4,%5,%6,%7}, {%8,%9}, {%0,%1,%2,%3};"
        : "+f"(d[0]), "+f"(d[1]), "+f"(d[2]), "+f"(d[3])
        : "r"(a[0]), "r"(a[1]), "r"(a[2]), "r"(a[3]), "r"(b[0]), "r"(b[1]));
}
__device__ __forceinline__ uint32_t pack_h2(float lo, float hi) {
    __half2 h = __floats2half2_rn(lo, hi);
    return *reinterpret_cast<uint32_t*>(&h);
}
__device__ __forceinline__ float gelu_exact(float v) {
    return 0.5f * v * (1.0f + erff(v * 0.70710678118654752f));
}

// ---------------- fp16 tensor-core GEMM --------------------------------------
// C[M,N] = A[M,K](half) @ Bt[N,K](half)^T + bias(f32).
// EPI: 0 = half out (+bias), 1 = half out (+bias, gelu), 2 = f32 out (+bias+res)
// CTA 128x128, 256 thr, warps 2(M)x4(N), warp tile 64x32, BK=32, 4 stages.
#define APH 40                      // half pitch (80 B rows; LDSM conflict-free)
#define TILE_HALF (128 * APH)       // 5120 halves = 10240 B per operand tile
#define STAGE_BYTES (2 * TILE_HALF * 2)   // 20480
#define GSTAGES 4
#define GEMM_SMEM (GSTAGES * STAGE_BYTES) // 81920

template <int EPI>
__global__ __launch_bounds__(256, 2) void gemm_h(
    const __half* __restrict__ A, const __half* __restrict__ Bt,
    const float* __restrict__ bias, const float* __restrict__ res,
    void* __restrict__ Cout, int K, int N)
{
    extern __shared__ char smemraw[];
    const uint32_t sb = smem_u32(smemraw);
    const int tid  = threadIdx.x;
    const int lane = tid & 31, wid = tid >> 5;
    const int warpM = wid & 1;
    const int warpN = wid >> 1;
    const int gID = lane >> 2, t4 = lane & 3;
    const int row0 = blockIdx.y * 128;
    const int col0 = blockIdx.x * 128;
    const int NC = K / 32;

    auto load_chunk = [&](int c, int s) {
        const int k0 = c * 32;
        const uint32_t as = sb + (uint32_t)s * STAGE_BYTES;
        const uint32_t bs = as + TILE_HALF * 2;
        #pragma unroll
        for (int i = 0; i < 2; i++) {   // A: 128 rows x 64B
            int ch = tid + i * 256;
            int r = ch >> 2, q = ch & 3;
            cp_async16(as + (uint32_t)(r * 80 + q * 16),
                       A + (size_t)(row0 + r) * K + k0 + q * 8);
        }
        #pragma unroll
        for (int i = 0; i < 2; i++) {   // B: 128 n-rows x 64B
            int ch = tid + i * 256;
            int r = ch >> 2, q = ch & 3;
            cp_async16(bs + (uint32_t)(r * 80 + q * 16),
                       Bt + (size_t)(col0 + r) * K + k0 + q * 8);
        }
    };

    #pragma unroll
    for (int c = 0; c < GSTAGES; c++) { load_chunk(c, c); cp_commit(); }

    float acc[4][4][4];
    #pragma unroll
    for (int i = 0; i < 4; i++)
        #pragma unroll
        for (int j = 0; j < 4; j++)
            #pragma unroll
            for (int e = 0; e < 4; e++) acc[i][j][e] = 0.f;

    const uint32_t lrow = (uint32_t)(lane & 15);
    const uint32_t lhi4 = (uint32_t)((lane >> 4) << 4);  // 0 or 16 bytes
    const uint32_t bln  = (uint32_t)(((lane >> 4) << 3) + (lane & 7));
    const uint32_t bhi  = (uint32_t)(((lane >> 3) & 1) << 4);

    for (int c = 0; c < NC; c++) {
        cp_wait<GSTAGES - 1>();
        __syncthreads();
        const uint32_t as = sb + (uint32_t)(c & 3) * STAGE_BYTES;
        const uint32_t bs = as + TILE_HALF * 2;

        #pragma unroll
        for (int ks = 0; ks < 2; ks++) {
            uint32_t a[4][4], bfr[2][4];
            #pragma unroll
            for (int am = 0; am < 4; am++)
                ldsm_x4(a[am], as + (uint32_t)(warpM * 64 + am * 16 + lrow) * 80
                               + ks * 32 + lhi4);
            #pragma unroll
            for (int bp = 0; bp < 2; bp++)
                ldsm_x4(bfr[bp], bs + (uint32_t)(warpN * 32 + bp * 16 + bln) * 80
                                 + ks * 32 + bhi);
            #pragma unroll
            for (int am = 0; am < 4; am++)
                #pragma unroll
                for (int an = 0; an < 4; an++)
                    mma_f16(acc[am][an], a[am], bfr[an >> 1] + (an & 1) * 2);
        }
        __syncthreads();
        if (c + GSTAGES < NC) load_chunk(c + GSTAGES, c & 3);
        cp_commit();
    }

    // epilogue
    #pragma unroll
    for (int am = 0; am < 4; am++) {
        const int rA = row0 + warpM * 64 + am * 16 + gID;
        #pragma unroll
        for (int hh = 0; hh < 2; hh++) {
            const int r = rA + hh * 8;
            #pragma unroll
            for (int an = 0; an < 4; an++) {
                const int cg = col0 + warpN * 32 + an * 8 + t4 * 2;
                float2 bv = *(const float2*)(bias + cg);
                float vx = acc[am][an][hh * 2 + 0] + bv.x;
                float vy = acc[am][an][hh * 2 + 1] + bv.y;
                if (EPI == 1) { vx = gelu_exact(vx); vy = gelu_exact(vy); }
                if (EPI <= 1) {
                    __half2 h = __floats2half2_rn(vx, vy);
                    *(__half2*)((__half*)Cout + (size_t)r * N + cg) = h;
                } else {
                    float2 rv = *(const float2*)(res + (size_t)r * N + cg);
                    float2 o; o.x = vx + rv.x; o.y = vy + rv.y;
                    *(float2*)((float*)Cout + (size_t)r * N + cg) = o;
                }
            }
        }
    }
}

// ---------------- prep kernels -------------------------------------------------
__global__ __launch_bounds__(256) void cvt_half_kernel(
    const float* __restrict__ in, __half* __restrict__ out, int n4)
{
    int i = blockIdx.x * 256 + threadIdx.x;
    if (i < n4) {
        float4 v = ((const float4*)in)[i];
        __half2 h0 = __floats2half2_rn(v.x, v.y);
        __half2 h1 = __floats2half2_rn(v.z, v.w);
        uint2 u; u.x = *(uint32_t*)&h0; u.y = *(uint32_t*)&h1;
        *(uint2*)(out + (size_t)i * 4) = u;
    }
}

// in [R][C] f32 -> out [C][R] half
__global__ __launch_bounds__(256) void transpose_cvt(
    const float* __restrict__ in, __half* __restrict__ out, int R, int C)
{
    __shared__ float sm[32][33];
    const int tx = threadIdx.x & 31, ty = threadIdx.x >> 5;
    const int r0 = blockIdx.y * 32, c0 = blockIdx.x * 32;
    #pragma unroll
    for (int i = 0; i < 4; i++)
        sm[ty + i * 8][tx] = in[(size_t)(r0 + ty + i * 8) * C + c0 + tx];
    __syncthreads();
    #pragma unroll
    for (int i = 0; i < 4; i++)
        out[(size_t)(c0 + ty + i * 8) * R + r0 + tx] =
            __float2half_rn(sm[tx][ty + i * 8]);
}

// ---------------- fp16 tensor-core flash attention -----------------------------
// grid (SQ/64, NH, BATCH), 128 thr (4 warps x 16 q). Tiles of 64 keys.
// Qs/Ks/Vs [64][72] half (LDSM conflict-free), Ms [64][68] f32.
#define AP 72
#define ATTN_SMEM (3 * 64 * AP * 2 + 64 * 68 * 4)   // 27648 + 17408 = 45056

__global__ __launch_bounds__(128, 4) void attn_h(
    const __half* __restrict__ QKV, const float* __restrict__ mask,
    __half* __restrict__ Ctx)
{
    extern __shared__ char smemraw[];
    const uint32_t qs = smem_u32(smemraw);
    const uint32_t ks = qs + 64 * AP * 2;
    const uint32_t vs = ks + 64 * AP * 2;
    float* Ms = (float*)(smemraw + 3 * 64 * AP * 2);
    const uint32_t ms = smem_u32(Ms);

    const int tid  = threadIdx.x;
    const int lane = tid & 31, w = tid >> 5;
    const int gID = lane >> 2, t4 = lane & 3;
    const int q0 = blockIdx.x * 64;
    const int h = blockIdx.y, b = blockIdx.z;
    const size_t tok0 = (size_t)b * SQ;
    const int qw = w * 16;

    const uint32_t lrow = (uint32_t)(lane & 15);
    const uint32_t lhi4 = (uint32_t)((lane >> 4) << 4);
    const uint32_t bln  = (uint32_t)(((lane >> 4) << 3) + (lane & 7));
    const uint32_t bhi  = (uint32_t)(((lane >> 3) & 1) << 4);
    const uint32_t vsel = (uint32_t)(lane >> 4);   // 0/1 for trans nd pair

    // Q tile: 64 rows x 128B via cp.async
    {
        const __half* src = QKV + (tok0 + q0) * QKVN + h * HD;
        #pragma unroll
        for (int j = 0; j < 4; j++) {
            int id = tid + j * 128;
            int r = id >> 3, q = id & 7;
            cp_async16(qs + (uint32_t)(r * 144 + q * 16), src + (size_t)r * QKVN + q * 8);
        }
        cp_commit();
    }

    float s[8][4], o[8][4];
    float m0 = -1e30f, m1 = -1e30f, l0 = 0.f, l1 = 0.f;
    #pragma unroll
    for (int j = 0; j < 8; j++)
        #pragma unroll
        for (int e = 0; e < 4; e++) o[j][e] = 0.f;

    for (int kt = 0; kt < SQ / 64; kt++) {
        const int k0g = kt * 64;
        const __half* ksrc = QKV + (tok0 + k0g) * QKVN + DM + h * HD;
        const __half* vsrc = ksrc + DM;
        #pragma unroll
        for (int j = 0; j < 4; j++) {
            int id = tid + j * 128;
            int r = id >> 3, q = id & 7;
            cp_async16(ks + (uint32_t)(r * 144 + q * 16), ksrc + (size_t)r * QKVN + q * 8);
            cp_async16(vs + (uint32_t)(r * 144 + q * 16), vsrc + (size_t)r * QKVN + q * 8);
        }
        const float* msrc = mask + ((size_t)b * SQ + q0) * SQ + k0g;
        #pragma unroll
        for (int j = 0; j < 8; j++) {
            int id = tid + j * 128;
            int r = id >> 4, q = id & 15;
            cp_async16(ms + (uint32_t)(r * 272 + q * 16), msrc + (size_t)r * SQ + q * 4);
        }
        cp_commit();
        cp_wait<0>();
        __syncthreads();

        // ---- scores = Q @ K^T ----
        #pragma unroll
        for (int j = 0; j < 8; j++)
            #pragma unroll
            for (int e = 0; e < 4; e++) s[j][e] = 0.f;
        #pragma unroll
        for (int c = 0; c < 4; c++) {
            uint32_t a[4];
            ldsm_x4(a, qs + (uint32_t)(qw + lrow) * 144 + c * 32 + lhi4);
            #pragma unroll
            for (int ap = 0; ap < 4; ap++) {
                uint32_t bfr[4];
                ldsm_x4(bfr, ks + (uint32_t)(ap * 16 + bln) * 144 + c * 32 + bhi);
                mma_f16(s[ap * 2 + 0], a, bfr);
                mma_f16(s[ap * 2 + 1], a, bfr + 2);
            }
        }

        // ---- scale + mask + online softmax ----
        float rmax0 = -1e30f, rmax1 = -1e30f;
        #pragma unroll
        for (int j = 0; j < 8; j++) {
            const float* mr0 = Ms + (qw + gID) * 68 + j * 8 + t4 * 2;
            const float* mr1 = mr0 + 8 * 68;
            float2 mv0 = *(const float2*)mr0;
            float2 mv1 = *(const float2*)mr1;
            s[j][0] = s[j][0] * 0.125f + mv0.x;
            s[j][1] = s[j][1] * 0.125f + mv0.y;
            s[j][2] = s[j][2] * 0.125f + mv1.x;
            s[j][3] = s[j][3] * 0.125f + mv1.y;
            rmax0 = fmaxf(rmax0, fmaxf(s[j][0], s[j][1]));
            rmax1 = fmaxf(rmax1, fmaxf(s[j][2], s[j][3]));
        }
        rmax0 = fmaxf(rmax0, __shfl_xor_sync(0xffffffffu, rmax0, 1));
        rmax0 = fmaxf(rmax0, __shfl_xor_sync(0xffffffffu, rmax0, 2));
        rmax1 = fmaxf(rmax1, __shfl_xor_sync(0xffffffffu, rmax1, 1));
        rmax1 = fmaxf(rmax1, __shfl_xor_sync(0xffffffffu, rmax1, 2));
        const float mn0 = fmaxf(m0, rmax0), mn1 = fmaxf(m1, rmax1);
        const float sc0 = __expf(m0 - mn0), sc1 = __expf(m1 - mn1);
        m0 = mn0; m1 = mn1;

        float ls0 = 0.f, ls1 = 0.f;
        #pragma unroll
        for (int j = 0; j < 8; j++) {
            s[j][0] = __expf(s[j][0] - mn0);
            s[j][1] = __expf(s[j][1] - mn0);
            s[j][2] = __expf(s[j][2] - mn1);
            s[j][3] = __expf(s[j][3] - mn1);
            ls0 += s[j][0] + s[j][1];
            ls1 += s[j][2] + s[j][3];
        }
        ls0 += __shfl_xor_sync(0xffffffffu, ls0, 1);
        ls0 += __shfl_xor_sync(0xffffffffu, ls0, 2);
        ls1 += __shfl_xor_sync(0xffffffffu, ls1, 1);
        ls1 += __shfl_xor_sync(0xffffffffu, ls1, 2);
        l0 = l0 * sc0 + ls0;
        l1 = l1 * sc1 + ls1;
        #pragma unroll
        for (int nd = 0; nd < 8; nd++) {
            o[nd][0] *= sc0; o[nd][1] *= sc0;
            o[nd][2] *= sc1; o[nd][3] *= sc1;
        }

        // ---- ctx += P @ V  (A-frag = packed accumulators; V^T via LDSM.trans) --
        #pragma unroll
        for (int j = 0; j < 4; j++) {
            uint32_t a[4];
            a[0] = pack_h2(s[2 * j][0],     s[2 * j][1]);
            a[1] = pack_h2(s[2 * j][2],     s[2 * j][3]);
            a[2] = pack_h2(s[2 * j + 1][0], s[2 * j + 1][1]);
            a[3] = pack_h2(s[2 * j + 1][2], s[2 * j + 1][3]);
            #pragma unroll
            for (int np = 0; np < 4; np++) {
                uint32_t bfr[4];
                ldsm_x4_t(bfr, vs + (uint32_t)(j * 16 + lrow) * 144
                               + (2 * np + vsel) * 16);
                mma_f16(o[2 * np + 0], a, bfr);
                mma_f16(o[2 * np + 1], a, bfr + 2);
            }
        }
        __syncthreads();
    }

    // ---- epilogue: normalize + cvt half + store ----
    const float il0 = 1.f / l0, il1 = 1.f / l1;
    __half* dst0 = Ctx + (tok0 + q0 + qw + gID) * DM + h * HD;
    __half* dst1 = dst0 + 8 * DM;
    #pragma unroll
    for (int nd = 0; nd < 8; nd++) {
        __half2 h0 = __floats2half2_rn(o[nd][0] * il0, o[nd][1] * il0);
        __half2 h1 = __floats2half2_rn(o[nd][2] * il1, o[nd][3] * il1);
        *(__half2*)(dst0 + nd * 8 + t4 * 2) = h0;
        *(__half2*)(dst1 + nd * 8 + t4 * 2) = h1;
    }
}

// ---------------- LayerNorm (f32 out + optional half copy) --------------------
template <bool HC>
__global__ __launch_bounds__(256) void ln_kernel(
    const float* __restrict__ X, const float* __restrict__ gam,
    const float* __restrict__ bet, float* __restrict__ O,
    __half* __restrict__ Oh)
{
    __shared__ float s1[8], s2[8];
    const int row = blockIdx.x;
    const int t = threadIdx.x;
    const float* x = X + (size_t)row * DM;
    const float a = x[t];
    const float c = x[t + 256];

    float sum = a + c;
    float sq  = a * a + c * c;
    #pragma unroll
    for (int o = 16; o; o >>= 1) {
        sum += __shfl_xor_sync(0xffffffffu, sum, o);
        sq  += __shfl_xor_sync(0xffffffffu, sq,  o);
    }
    if ((t & 31) == 0) { s1[t >> 5] = sum; s2[t >> 5] = sq; }
    __syncthreads();
    sum = 0.f; sq = 0.f;
    #pragma unroll
    for (int i = 0; i < 8; i++) { sum += s1[i]; sq += s2[i]; }

    const float mu  = sum * (1.0f / DM);
    const float var = sq * (1.0f / DM) - mu * mu;
    const float inv = rsqrtf(var + 1e-12f);

    const float o0 = (a - mu) * inv * gam[t]       + bet[t];
    const float o1 = (c - mu) * inv * gam[t + 256] + bet[t + 256];
    O[(size_t)row * DM + t]       = o0;
    O[(size_t)row * DM + t + 256] = o1;
    if (HC) {
        Oh[(size_t)row * DM + t]       = __float2half_rn(o0);
        Oh[(size_t)row * DM + t + 256] = __float2half_rn(o1);
    }
}

// ---------------- launch -------------------------------------------------------
extern "C" void kernel_launch(void* const* d_in, const int* in_sizes, int n_in,
                              void* d_out, int out_size)
{
    const float* x    = (const float*)d_in[0];
    const float* mask = (const float*)d_in[1];
    const float* Wq   = (const float*)d_in[2];
    const float* bq   = (const float*)d_in[3];
    const float* Wk   = (const float*)d_in[4];
    const float* bk   = (const float*)d_in[5];
    const float* Wv   = (const float*)d_in[6];
    const float* bv   = (const float*)d_in[7];
    const float* Wo   = (const float*)d_in[8];
    const float* bo   = (const float*)d_in[9];
    const float* ln1g = (const float*)d_in[10];
    const float* ln1b = (const float*)d_in[11];
    const float* W1   = (const float*)d_in[12];
    const float* b1   = (const float*)d_in[13];
    const float* W2   = (const float*)d_in[14];
    const float* b2   = (const float*)d_in[15];
    const float* ln2g = (const float*)d_in[16];
    const float* ln2b = (const float*)d_in[17];
    float* out = (float*)d_out;

    __half *xh, *QKV, *Ctx, *Ahf, *H, *Wqkvt, *Wot, *W1t, *W2t;
    float *T1, *A, *T2, *bqkv;
    cudaGetSymbolAddress((void**)&xh,    g_xh);
    cudaGetSymbolAddress((void**)&QKV,   g_QKV);
    cudaGetSymbolAddress((void**)&Ctx,   g_Ctx);
    cudaGetSymbolAddress((void**)&Ahf,   g_Ahf);
    cudaGetSymbolAddress((void**)&H,     g_H);
    cudaGetSymbolAddress((void**)&Wqkvt, g_Wqkvt);
    cudaGetSymbolAddress((void**)&Wot,   g_Wot);
    cudaGetSymbolAddress((void**)&W1t,   g_W1t);
    cudaGetSymbolAddress((void**)&W2t,   g_W2t);
    cudaGetSymbolAddress((void**)&T1,    g_T1);
    cudaGetSymbolAddress((void**)&A,     g_A);
    cudaGetSymbolAddress((void**)&T2,    g_T2);
    cudaGetSymbolAddress((void**)&bqkv,  g_bqkv);

    cudaFuncSetAttribute(gemm_h<0>, cudaFuncAttributeMaxDynamicSharedMemorySize, GEMM_SMEM);
    cudaFuncSetAttribute(gemm_h<1>, cudaFuncAttributeMaxDynamicSharedMemorySize, GEMM_SMEM);
    cudaFuncSetAttribute(gemm_h<2>, cudaFuncAttributeMaxDynamicSharedMemorySize, GEMM_SMEM);
    cudaFuncSetAttribute(attn_h,    cudaFuncAttributeMaxDynamicSharedMemorySize, ATTN_SMEM);

    dim3 thr(256);

    // prep: cvt x; transpose+cvt weights; concat biases
    cvt_half_kernel<<<TOKENS * DM / 4 / 256, thr>>>(x, xh, TOKENS * DM / 4);
    transpose_cvt<<<dim3(16, 16), thr>>>(Wq, Wqkvt + 0 * DM * DM, DM, DM);
    transpose_cvt<<<dim3(16, 16), thr>>>(Wk, Wqkvt + 1 * DM * DM, DM, DM);
    transpose_cvt<<<dim3(16, 16), thr>>>(Wv, Wqkvt + 2 * DM * DM, DM, DM);
    transpose_cvt<<<dim3(16, 16), thr>>>(Wo, Wot, DM, DM);
    transpose_cvt<<<dim3(64, 16), thr>>>(W1, W1t, DM, DFF);
    transpose_cvt<<<dim3(16, 64), thr>>>(W2, W2t, DFF, DM);
    cudaMemcpyAsync(bqkv + 0 * DM, bq, DM * sizeof(float), cudaMemcpyDeviceToDevice);
    cudaMemcpyAsync(bqkv + 1 * DM, bk, DM * sizeof(float), cudaMemcpyDeviceToDevice);
    cudaMemcpyAsync(bqkv + 2 * DM, bv, DM * sizeof(float), cudaMemcpyDeviceToDevice);

    // fused QKV projection -> half
    gemm_h<0><<<dim3(QKVN / 128, TOKENS / 128), thr, GEMM_SMEM>>>(
        xh, Wqkvt, bqkv, nullptr, QKV, DM, QKVN);

    // fp16 tensor-core flash attention -> half
    attn_h<<<dim3(SQ / 64, NH, BATCH), dim3(128), ATTN_SMEM>>>(QKV, mask, Ctx);

    // O projection + residual(x) -> f32, LN1 (f32 + half copy)
    gemm_h<2><<<dim3(DM / 128, TOKENS / 128), thr, GEMM_SMEM>>>(
        Ctx, Wot, bo, x, T1, DM, DM);
    ln_kernel<true><<<TOKENS, thr>>>(T1, ln1g, ln1b, A, Ahf);

    // FFN
    gemm_h<1><<<dim3(DFF / 128, TOKENS / 128), thr, GEMM_SMEM>>>(
        Ahf, W1t, b1, nullptr, H, DM, DFF);
    gemm_h<2><<<dim3(DM / 128, TOKENS / 128), thr, GEMM_SMEM>>>(
        H, W2t, b2, A, T2, DFF, DM);
    ln_kernel<false><<<TOKENS, thr>>>(T2, ln2g, ln2b, out, nullptr);
}